// round 1
// baseline (speedup 1.0000x reference)
#include <cuda_runtime.h>
#include <cuda_bf16.h>
#include <math.h>
#include <stdint.h>

// ---------------------------------------------------------------------------
// ChunkStickyRouter: router MLP (2048->1024->512->8) + per-chunk mean +
// argmax/hysteresis + one-hot routing weights + stats.
// B=4, S=4096, D=2048, H=1024, E=8, CHUNK=128 -> 16384 tokens, 128 chunks.
// ---------------------------------------------------------------------------

#define BM 128
#define BN 128
#define BK 32
#define LDA 36    // floats; 36*4=144 bytes (16B aligned rows, conflict-free frags)
#define LDB 136   // floats; 136*4=544 bytes (16B aligned rows, conflict-free frags)

#define NTOK  16384
#define DIM   2048
#define HID   1024
#define HID2  512
#define NEXP  8
#define NCHUNK 128   // B*C = 4*32
#define CSEQ   32    // chunks per sequence

// output layout (float32, concatenated reference outputs)
#define OFF_RW    0          // routing_weights  [4,4096,8] = 131072
#define OFF_EIDX  131072     // expert_indices   [4,32]     = 128
#define OFF_CLOG  131200     // chunk_logits     [4,32,8]   = 1024
#define OFF_ENT   132224     // gate_entropy
#define OFF_UTIL  132225     // expert_utilization [8]
#define OFF_FLIP  132233     // flip_rate
#define OFF_CONC  132234     // routing_concentration

// scratch (no cudaMalloc allowed)
__device__ float g_h1[(size_t)NTOK * HID];   // 64 MB hidden1
__device__ float g_S[NCHUNK * HID2];         // per-chunk column sums of h2
__device__ float g_logits[NCHUNK * NEXP];    // chunk logits
__device__ int   g_expert[NCHUNK];           // final expert per chunk

__device__ __forceinline__ float to_tf32(float x) {
    asm("cvt.rna.tf32.f32 %0, %0;" : "+f"(x));
    return x;
}

__device__ __forceinline__ void mma_tf32(float& d0, float& d1, float& d2, float& d3,
                                         unsigned a0, unsigned a1, unsigned a2, unsigned a3,
                                         unsigned b0, unsigned b1) {
    asm volatile(
        "mma.sync.aligned.m16n8k8.row.col.f32.tf32.tf32.f32 "
        "{%0,%1,%2,%3},{%4,%5,%6,%7},{%8,%9},{%0,%1,%2,%3};\n"
        : "+f"(d0), "+f"(d1), "+f"(d2), "+f"(d3)
        : "r"(a0), "r"(a1), "r"(a2), "r"(a3), "r"(b0), "r"(b1));
}

// EPI==0: C[m][n] = relu(acc + bias[n])  (store full output)
// EPI==1: per-chunk (BM=128=CHUNK rows) column sums of relu(acc + bias[n]) -> Sout
template <int EPI>
__global__ __launch_bounds__(256, 1)
void gemm_relu(const float* __restrict__ A, const float* __restrict__ B,
               const float* __restrict__ bias, float* __restrict__ C,
               float* __restrict__ Sout, int M, int N, int K) {
    __shared__ __align__(16) float As[BM * LDA];
    __shared__ __align__(16) float Bs[BK * LDB];
    __shared__ float colsum[BN];

    const int tid = threadIdx.x;
    const int warp = tid >> 5;
    const int lane = tid & 31;
    const int g = lane >> 2;   // groupID (row within mma tile)
    const int tg = lane & 3;   // thread-in-group
    const int warpM = warp >> 2;  // 0..1 (64 rows each)
    const int warpN = warp & 3;   // 0..3 (32 cols each)
    const int bm = blockIdx.y, bn = blockIdx.x;

    const float* Ablk = A + (size_t)bm * BM * K;
    const float* Bblk = B + (size_t)bn * BN;

    if (EPI == 1 && tid < BN) colsum[tid] = 0.f;

    float acc[4][4][4];
#pragma unroll
    for (int i = 0; i < 4; i++)
#pragma unroll
        for (int j = 0; j < 4; j++)
#pragma unroll
            for (int r = 0; r < 4; r++) acc[i][j][r] = 0.f;

    float4 pa[4], pb[4];

    auto ldg_tile = [&](int kt) {
#pragma unroll
        for (int i = 0; i < 4; i++) {
            int f = tid + 256 * i;
            int row = f >> 3, c4 = f & 7;  // A: 128 rows x 8 float4
            pa[i] = *(const float4*)(Ablk + (size_t)row * K + (size_t)kt * BK + c4 * 4);
        }
#pragma unroll
        for (int i = 0; i < 4; i++) {
            int f = tid + 256 * i;
            int row = f >> 5, c4 = f & 31; // B: 32 rows x 32 float4
            pb[i] = *(const float4*)(Bblk + (size_t)(kt * BK + row) * N + c4 * 4);
        }
    };

    auto sts_tile = [&]() {
#pragma unroll
        for (int i = 0; i < 4; i++) {
            int f = tid + 256 * i;
            int row = f >> 3, c4 = f & 7;
            float4 v = pa[i];
            v.x = to_tf32(v.x); v.y = to_tf32(v.y);
            v.z = to_tf32(v.z); v.w = to_tf32(v.w);
            *(float4*)(As + row * LDA + c4 * 4) = v;
        }
#pragma unroll
        for (int i = 0; i < 4; i++) {
            int f = tid + 256 * i;
            int row = f >> 5, c4 = f & 31;
            float4 v = pb[i];
            v.x = to_tf32(v.x); v.y = to_tf32(v.y);
            v.z = to_tf32(v.z); v.w = to_tf32(v.w);
            *(float4*)(Bs + row * LDB + c4 * 4) = v;
        }
    };

    const uint32_t* Asu = (const uint32_t*)As;
    const uint32_t* Bsu = (const uint32_t*)Bs;

    auto compute_tile = [&]() {
#pragma unroll
        for (int kk = 0; kk < 4; kk++) {
            const int k0 = kk * 8;
            unsigned af[4][4], bf[4][2];
#pragma unroll
            for (int mi = 0; mi < 4; mi++) {
                int r0 = warpM * 64 + mi * 16;
                af[mi][0] = Asu[(r0 + g) * LDA + k0 + tg];
                af[mi][1] = Asu[(r0 + 8 + g) * LDA + k0 + tg];
                af[mi][2] = Asu[(r0 + g) * LDA + k0 + 4 + tg];
                af[mi][3] = Asu[(r0 + 8 + g) * LDA + k0 + 4 + tg];
            }
#pragma unroll
            for (int ni = 0; ni < 4; ni++) {
                int n0 = warpN * 32 + ni * 8 + g;
                bf[ni][0] = Bsu[(k0 + tg) * LDB + n0];
                bf[ni][1] = Bsu[(k0 + 4 + tg) * LDB + n0];
            }
#pragma unroll
            for (int mi = 0; mi < 4; mi++)
#pragma unroll
                for (int ni = 0; ni < 4; ni++)
                    mma_tf32(acc[mi][ni][0], acc[mi][ni][1], acc[mi][ni][2], acc[mi][ni][3],
                             af[mi][0], af[mi][1], af[mi][2], af[mi][3],
                             bf[ni][0], bf[ni][1]);
        }
    };

    const int KT = K / BK;
    ldg_tile(0);
    sts_tile();
    __syncthreads();
    for (int kt = 1; kt < KT; kt++) {
        ldg_tile(kt);        // prefetch next tile into registers
        compute_tile();      // compute current smem tile (hides LDG latency)
        __syncthreads();
        sts_tile();
        __syncthreads();
    }
    compute_tile();

    if (EPI == 0) {
#pragma unroll
        for (int mi = 0; mi < 4; mi++) {
            int mrow = bm * BM + warpM * 64 + mi * 16 + g;
#pragma unroll
            for (int ni = 0; ni < 4; ni++) {
                int ncol = bn * BN + warpN * 32 + ni * 8 + 2 * tg;
                float bv0 = bias[ncol], bv1 = bias[ncol + 1];
                float2 v0 = {fmaxf(acc[mi][ni][0] + bv0, 0.f),
                             fmaxf(acc[mi][ni][1] + bv1, 0.f)};
                float2 v1 = {fmaxf(acc[mi][ni][2] + bv0, 0.f),
                             fmaxf(acc[mi][ni][3] + bv1, 0.f)};
                *(float2*)(C + (size_t)mrow * N + ncol) = v0;
                *(float2*)(C + (size_t)(mrow + 8) * N + ncol) = v1;
            }
        }
    } else {
        // per-chunk column sums: BM=128 rows of this CTA == exactly one chunk
#pragma unroll
        for (int ni = 0; ni < 4; ni++) {
#pragma unroll
            for (int p = 0; p < 2; p++) {
                int nloc = warpN * 32 + ni * 8 + 2 * tg + p;
                float bv = bias[bn * BN + nloc];
                float s = 0.f;
#pragma unroll
                for (int mi = 0; mi < 4; mi++) {
                    s += fmaxf(acc[mi][ni][p] + bv, 0.f);       // row g
                    s += fmaxf(acc[mi][ni][p + 2] + bv, 0.f);   // row g+8
                }
                // reduce over g (lanes xor 4,8,16 share tig/column)
                s += __shfl_xor_sync(0xffffffffu, s, 4);
                s += __shfl_xor_sync(0xffffffffu, s, 8);
                s += __shfl_xor_sync(0xffffffffu, s, 16);
                if (g == 0) atomicAdd(&colsum[nloc], s);
            }
        }
        __syncthreads();
        if (tid < BN)
            Sout[(size_t)bm * N + bn * BN + tid] = colsum[tid];
    }
}

// chunk_logits[c][e] = (1/128) * S[c][:] . w3[:,e] + b3[e]   (linearity of w3)
__global__ void chunk_logits_kernel(const float* __restrict__ w3,
                                    const float* __restrict__ b3,
                                    float* __restrict__ out) {
    const int c = blockIdx.x;    // 0..127
    const int tid = threadIdx.x; // 256
    float partial[8];
#pragma unroll
    for (int e = 0; e < 8; e++) partial[e] = 0.f;
    for (int k = tid; k < HID2; k += 256) {
        float sv = g_S[c * HID2 + k];
        float4 wa = *(const float4*)(w3 + k * 8);
        float4 wb = *(const float4*)(w3 + k * 8 + 4);
        partial[0] += sv * wa.x; partial[1] += sv * wa.y;
        partial[2] += sv * wa.z; partial[3] += sv * wa.w;
        partial[4] += sv * wb.x; partial[5] += sv * wb.y;
        partial[6] += sv * wb.z; partial[7] += sv * wb.w;
    }
    __shared__ float red[256][8];
#pragma unroll
    for (int e = 0; e < 8; e++) red[tid][e] = partial[e];
    __syncthreads();
    for (int s2 = 128; s2 > 0; s2 >>= 1) {
        if (tid < s2) {
#pragma unroll
            for (int e = 0; e < 8; e++) red[tid][e] += red[tid + s2][e];
        }
        __syncthreads();
    }
    if (tid < 8) {
        float v = red[0][tid] * (1.f / 128.f) + b3[tid];
        g_logits[c * 8 + tid] = v;
        out[OFF_CLOG + c * 8 + tid] = v;
    }
}

// argmax + sequential hysteresis + stats. 1 CTA, 1 warp; lanes 0..3 = batches.
__global__ void stats_kernel(float* __restrict__ out) {
    const int lane = threadIdx.x;
    int cnt[8];
#pragma unroll
    for (int e = 0; e < 8; e++) cnt[e] = 0;
    float entsum = 0.f;
    int flips = 0;

    if (lane < 4) {
        const int b = lane;
        int prev = 0;
        for (int c = 0; c < CSEQ; c++) {
            float lg[8];
#pragma unroll
            for (int e = 0; e < 8; e++) lg[e] = g_logits[(b * CSEQ + c) * 8 + e];
            int top = 0;
            float best = lg[0];
#pragma unroll
            for (int e = 1; e < 8; e++)
                if (lg[e] > best) { best = lg[e]; top = e; }
            int fin;
            if (c == 0) {
                fin = top;
            } else {
                bool sw = (lg[top] - lg[prev]) > 0.7f;
                if (sw) flips++;
                fin = sw ? top : prev;
            }
            prev = fin;
            g_expert[b * CSEQ + c] = fin;
            out[OFF_EIDX + b * CSEQ + c] = (float)fin;
            cnt[fin]++;
            // entropy of softmax
            float mx = lg[0];
#pragma unroll
            for (int e = 1; e < 8; e++) mx = fmaxf(mx, lg[e]);
            float ex[8], se = 0.f;
#pragma unroll
            for (int e = 0; e < 8; e++) { ex[e] = expf(lg[e] - mx); se += ex[e]; }
            float inv = 1.f / se;
            float ent = 0.f;
#pragma unroll
            for (int e = 0; e < 8; e++) {
                float p = ex[e] * inv;
                ent -= p * logf(p + 1e-8f);
            }
            entsum += ent;
        }
    }
    // reduce across warp (lanes >=4 contribute zeros)
    for (int off = 16; off > 0; off >>= 1) {
        entsum += __shfl_xor_sync(0xffffffffu, entsum, off);
        flips += __shfl_xor_sync(0xffffffffu, flips, off);
#pragma unroll
        for (int e = 0; e < 8; e++)
            cnt[e] += __shfl_xor_sync(0xffffffffu, cnt[e], off);
    }
    if (lane == 0) {
        out[OFF_ENT] = entsum / (float)NCHUNK;
        float nrm = 0.f;
#pragma unroll
        for (int e = 0; e < 8; e++) {
            float u = (float)cnt[e] / (float)NCHUNK;
            out[OFF_UTIL + e] = u;
            nrm += u * u;
        }
        out[OFF_FLIP] = (float)flips / (4.f * 31.f);
        out[OFF_CONC] = sqrtf(nrm);
    }
}

// routing_weights[b][s][e] = one_hot(expert[b][s/128])  -> 131072 floats
__global__ void rw_kernel(float* __restrict__ out) {
    int i = blockIdx.x * blockDim.x + threadIdx.x;  // float4 index, 32768 total
    int o = i << 2;
    int ex = g_expert[o >> 10];   // o / (128 tokens * 8 experts)
    int e0 = o & 7;
    float4 v;
    v.x = (e0 == ex) ? 1.f : 0.f;
    v.y = (e0 + 1 == ex) ? 1.f : 0.f;
    v.z = (e0 + 2 == ex) ? 1.f : 0.f;
    v.w = (e0 + 3 == ex) ? 1.f : 0.f;
    ((float4*)(out + OFF_RW))[i] = v;
}

extern "C" void kernel_launch(void* const* d_in, const int* in_sizes, int n_in,
                              void* d_out, int out_size) {
    const float* x  = (const float*)d_in[0];
    // d_in[1] = prev_expert_indices: unused by the reference computation
    const float* w1 = (const float*)d_in[2];
    const float* b1 = (const float*)d_in[3];
    const float* w2 = (const float*)d_in[4];
    const float* b2 = (const float*)d_in[5];
    const float* w3 = (const float*)d_in[6];
    const float* b3 = (const float*)d_in[7];
    float* out = (float*)d_out;

    float *h1, *S;
    cudaGetSymbolAddress((void**)&h1, g_h1);
    cudaGetSymbolAddress((void**)&S, g_S);

    // GEMM1: h1 = relu(x @ w1 + b1)   [16384,2048]x[2048,1024]
    gemm_relu<0><<<dim3(HID / BN, NTOK / BM), 256>>>(x, w1, b1, h1, nullptr,
                                                     NTOK, HID, DIM);
    // GEMM2: S[chunk][n] = sum_{128 tokens} relu(h1 @ w2 + b2)  (h2 never stored)
    gemm_relu<1><<<dim3(HID2 / BN, NTOK / BM), 256>>>(h1, w2, b2, nullptr, S,
                                                      NTOK, HID2, HID);
    // chunk logits via linearity of the final layer
    chunk_logits_kernel<<<NCHUNK, 256>>>(w3, b3, out);
    // argmax / hysteresis / stats
    stats_kernel<<<1, 32>>>(out);
    // one-hot routing weights
    rw_kernel<<<128, 256>>>(out);
}

// round 5
// speedup vs baseline: 1.2008x; 1.2008x over previous
#include <cuda_runtime.h>
#include <cuda_bf16.h>
#include <math.h>
#include <stdint.h>

// ---------------------------------------------------------------------------
// ChunkStickyRouter: router MLP (2048->1024->512->8) + per-chunk mean +
// argmax/hysteresis + one-hot routing weights + stats.
// B=4, S=4096, D=2048, H=1024, E=8, CHUNK=128 -> 16384 tokens, 128 chunks.
// R5: cp.async pipelined tf32 GEMM with proper RNA rounding:
//     weights pre-rounded once; GEMM1 rounds A-frags in regs; h1 stored
//     pre-rounded so GEMM2 has zero in-loop cvts.
// ---------------------------------------------------------------------------

#define BM 128
#define BN 128
#define BK 32
#define LDA 36    // floats; conflict-free A frag LDS, 16B-aligned rows
#define LDB 136   // floats; conflict-free B frag LDS, 16B-aligned rows
#define NSTAGE 3

#define NTOK  16384
#define DIM   2048
#define HID   1024
#define HID2  512
#define NEXP  8
#define NCHUNK 128   // B*C = 4*32
#define CSEQ   32    // chunks per sequence

// output layout (float32, concatenated reference outputs)
#define OFF_RW    0          // routing_weights  [4,4096,8] = 131072
#define OFF_EIDX  131072     // expert_indices   [4,32]     = 128
#define OFF_CLOG  131200     // chunk_logits     [4,32,8]   = 1024
#define OFF_ENT   132224     // gate_entropy
#define OFF_UTIL  132225     // expert_utilization [8]
#define OFF_FLIP  132233     // flip_rate
#define OFF_CONC  132234     // routing_concentration

#define SMEM_STAGE_A (BM * LDA)            // 4608 floats
#define SMEM_STAGE_B (BK * LDB)            // 4352 floats
#define SMEM_BYTES (NSTAGE * (SMEM_STAGE_A + SMEM_STAGE_B) * 4)   // 107520 B

// scratch (no cudaMalloc allowed)
__device__ float g_h1[(size_t)NTOK * HID];   // 64 MB hidden1 (stored tf32-rounded)
__device__ float g_w1r[(size_t)DIM * HID];   // 8 MB  w1 RNA-rounded to tf32
__device__ float g_w2r[(size_t)HID * HID2];  // 2 MB  w2 RNA-rounded to tf32
__device__ float g_S[NCHUNK * HID2];         // per-chunk column sums of h2
__device__ float g_logits[NCHUNK * NEXP];    // chunk logits
__device__ int   g_expert[NCHUNK];           // final expert per chunk

__device__ __forceinline__ float to_tf32(float x) {
    asm("cvt.rna.tf32.f32 %0, %0;" : "+f"(x));
    return x;
}
__device__ __forceinline__ unsigned to_tf32_u(unsigned x) {
    float f = __uint_as_float(x);
    asm("cvt.rna.tf32.f32 %0, %0;" : "+f"(f));
    return __float_as_uint(f);
}

__device__ __forceinline__ void cp16(float* dst, const float* src) {
    uint32_t d = (uint32_t)__cvta_generic_to_shared(dst);
    asm volatile("cp.async.cg.shared.global [%0], [%1], 16;\n" :: "r"(d), "l"(src));
}

__device__ __forceinline__ void mma_tf32(float& d0, float& d1, float& d2, float& d3,
                                         unsigned a0, unsigned a1, unsigned a2, unsigned a3,
                                         unsigned b0, unsigned b1) {
    asm volatile(
        "mma.sync.aligned.m16n8k8.row.col.f32.tf32.tf32.f32 "
        "{%0,%1,%2,%3},{%4,%5,%6,%7},{%8,%9},{%0,%1,%2,%3};\n"
        : "+f"(d0), "+f"(d1), "+f"(d2), "+f"(d3)
        : "r"(a0), "r"(a1), "r"(a2), "r"(a3), "r"(b0), "r"(b1));
}

// RNA-round w1 and w2 into scratch (one-time per launch, ~5us)
__global__ void round_weights_kernel(const float* __restrict__ w1,
                                     const float* __restrict__ w2) {
    const int n1 = DIM * HID / 4;        // 524288 float4
    const int n2 = HID * HID2 / 4;       // 131072 float4
    int i = blockIdx.x * blockDim.x + threadIdx.x;
    if (i < n1) {
        float4 v = ((const float4*)w1)[i];
        v.x = to_tf32(v.x); v.y = to_tf32(v.y);
        v.z = to_tf32(v.z); v.w = to_tf32(v.w);
        ((float4*)g_w1r)[i] = v;
    } else if (i < n1 + n2) {
        int j = i - n1;
        float4 v = ((const float4*)w2)[j];
        v.x = to_tf32(v.x); v.y = to_tf32(v.y);
        v.z = to_tf32(v.z); v.w = to_tf32(v.w);
        ((float4*)g_w2r)[j] = v;
    }
}

// EPI==0: C[m][n] = tf32_round(relu(acc + bias[n]))  (store full output)
// EPI==1: per-chunk (BM=128=CHUNK rows) column sums of relu(acc + bias[n]) -> Sout
// CVT_A==1: RNA-round A fragments in registers (A not pre-rounded)
template <int EPI, int CVT_A>
__global__ __launch_bounds__(256)
void gemm_relu(const float* __restrict__ A, const float* __restrict__ B,
               const float* __restrict__ bias, float* __restrict__ C,
               float* __restrict__ Sout, int M, int N, int K) {
    extern __shared__ __align__(16) float smem[];
    float* As = smem;                              // NSTAGE * BM*LDA
    float* Bs = smem + NSTAGE * SMEM_STAGE_A;      // NSTAGE * BK*LDB
    __shared__ float colsum[BN];

    const int tid = threadIdx.x;
    const int warp = tid >> 5;
    const int lane = tid & 31;
    const int g = lane >> 2;   // groupID (row within mma tile)
    const int tg = lane & 3;   // thread-in-group
    const int warpM = warp >> 2;  // 0..1 (64 rows each)
    const int warpN = warp & 3;   // 0..3 (32 cols each)
    const int bm = blockIdx.y, bn = blockIdx.x;

    const float* Ablk = A + (size_t)bm * BM * K;
    const float* Bblk = B + (size_t)bn * BN;

    if (EPI == 1 && tid < BN) colsum[tid] = 0.f;

    float acc[4][4][4];
#pragma unroll
    for (int i = 0; i < 4; i++)
#pragma unroll
        for (int j = 0; j < 4; j++)
#pragma unroll
            for (int r = 0; r < 4; r++) acc[i][j][r] = 0.f;

    // precomputed per-thread load coordinates
    const int arow = tid >> 3, ac4 = (tid & 7) * 4;     // +32 rows per i
    const int brow = tid >> 5, bc4 = (tid & 31) * 4;    // +8 rows per i

    auto issue = [&](int kt) {
        const int st = kt % NSTAGE;
        float* Ad = As + st * SMEM_STAGE_A;
        float* Bd = Bs + st * SMEM_STAGE_B;
        const float* Ag = Ablk + (size_t)kt * BK;
        const float* Bg = Bblk + (size_t)kt * BK * N;
#pragma unroll
        for (int i = 0; i < 4; i++) {
            int r = arow + 32 * i;
            cp16(Ad + r * LDA + ac4, Ag + (size_t)r * K + ac4);
        }
#pragma unroll
        for (int i = 0; i < 4; i++) {
            int r = brow + 8 * i;
            cp16(Bd + r * LDB + bc4, Bg + (size_t)r * N + bc4);
        }
        asm volatile("cp.async.commit_group;\n");
    };

    auto compute_tile = [&](int st) {
        const uint32_t* Asu = (const uint32_t*)(As + st * SMEM_STAGE_A);
        const uint32_t* Bsu = (const uint32_t*)(Bs + st * SMEM_STAGE_B);
#pragma unroll
        for (int kk = 0; kk < 4; kk++) {
            const int k0 = kk * 8;
            unsigned af[4][4], bf[4][2];
#pragma unroll
            for (int mi = 0; mi < 4; mi++) {
                int r0 = warpM * 64 + mi * 16;
                af[mi][0] = Asu[(r0 + g) * LDA + k0 + tg];
                af[mi][1] = Asu[(r0 + 8 + g) * LDA + k0 + tg];
                af[mi][2] = Asu[(r0 + g) * LDA + k0 + 4 + tg];
                af[mi][3] = Asu[(r0 + 8 + g) * LDA + k0 + 4 + tg];
                if (CVT_A) {
                    af[mi][0] = to_tf32_u(af[mi][0]);
                    af[mi][1] = to_tf32_u(af[mi][1]);
                    af[mi][2] = to_tf32_u(af[mi][2]);
                    af[mi][3] = to_tf32_u(af[mi][3]);
                }
            }
#pragma unroll
            for (int ni = 0; ni < 4; ni++) {
                int n0 = warpN * 32 + ni * 8 + g;
                bf[ni][0] = Bsu[(k0 + tg) * LDB + n0];
                bf[ni][1] = Bsu[(k0 + 4 + tg) * LDB + n0];
            }
#pragma unroll
            for (int mi = 0; mi < 4; mi++)
#pragma unroll
                for (int ni = 0; ni < 4; ni++)
                    mma_tf32(acc[mi][ni][0], acc[mi][ni][1], acc[mi][ni][2], acc[mi][ni][3],
                             af[mi][0], af[mi][1], af[mi][2], af[mi][3],
                             bf[ni][0], bf[ni][1]);
        }
    };

    const int KT = K / BK;
    issue(0);
    issue(1);
    for (int kt = 0; kt < KT; kt++) {
        asm volatile("cp.async.wait_group 1;\n");
        __syncthreads();
        if (kt + 2 < KT) issue(kt + 2);
        else asm volatile("cp.async.commit_group;\n");
        compute_tile(kt % NSTAGE);
    }

    if (EPI == 0) {
        // store tf32-rounded so GEMM2 needs no in-loop A conversion
#pragma unroll
        for (int mi = 0; mi < 4; mi++) {
            int mrow = bm * BM + warpM * 64 + mi * 16 + g;
#pragma unroll
            for (int ni = 0; ni < 4; ni++) {
                int ncol = bn * BN + warpN * 32 + ni * 8 + 2 * tg;
                float bv0 = bias[ncol], bv1 = bias[ncol + 1];
                float2 v0 = {to_tf32(fmaxf(acc[mi][ni][0] + bv0, 0.f)),
                             to_tf32(fmaxf(acc[mi][ni][1] + bv1, 0.f))};
                float2 v1 = {to_tf32(fmaxf(acc[mi][ni][2] + bv0, 0.f)),
                             to_tf32(fmaxf(acc[mi][ni][3] + bv1, 0.f))};
                *(float2*)(C + (size_t)mrow * N + ncol) = v0;
                *(float2*)(C + (size_t)(mrow + 8) * N + ncol) = v1;
            }
        }
    } else {
        // per-chunk column sums: BM=128 rows of this CTA == exactly one chunk
#pragma unroll
        for (int ni = 0; ni < 4; ni++) {
#pragma unroll
            for (int p = 0; p < 2; p++) {
                int nloc = warpN * 32 + ni * 8 + 2 * tg + p;
                float bv = bias[bn * BN + nloc];
                float s = 0.f;
#pragma unroll
                for (int mi = 0; mi < 4; mi++) {
                    s += fmaxf(acc[mi][ni][p] + bv, 0.f);       // row g
                    s += fmaxf(acc[mi][ni][p + 2] + bv, 0.f);   // row g+8
                }
                // reduce over g (lanes xor 4,8,16 share same output column)
                s += __shfl_xor_sync(0xffffffffu, s, 4);
                s += __shfl_xor_sync(0xffffffffu, s, 8);
                s += __shfl_xor_sync(0xffffffffu, s, 16);
                if (g == 0) atomicAdd(&colsum[nloc], s);
            }
        }
        __syncthreads();
        if (tid < BN)
            Sout[(size_t)bm * N + bn * BN + tid] = colsum[tid];
    }
}

// chunk_logits[c][e] = (1/128) * S[c][:] . w3[:,e] + b3[e]   (linearity of w3)
__global__ void chunk_logits_kernel(const float* __restrict__ w3,
                                    const float* __restrict__ b3,
                                    float* __restrict__ out) {
    const int c = blockIdx.x;    // 0..127
    const int tid = threadIdx.x; // 256
    float partial[8];
#pragma unroll
    for (int e = 0; e < 8; e++) partial[e] = 0.f;
    for (int k = tid; k < HID2; k += 256) {
        float sv = g_S[c * HID2 + k];
        float4 wa = *(const float4*)(w3 + k * 8);
        float4 wb = *(const float4*)(w3 + k * 8 + 4);
        partial[0] += sv * wa.x; partial[1] += sv * wa.y;
        partial[2] += sv * wa.z; partial[3] += sv * wa.w;
        partial[4] += sv * wb.x; partial[5] += sv * wb.y;
        partial[6] += sv * wb.z; partial[7] += sv * wb.w;
    }
    __shared__ float red[256][8];
#pragma unroll
    for (int e = 0; e < 8; e++) red[tid][e] = partial[e];
    __syncthreads();
    for (int s2 = 128; s2 > 0; s2 >>= 1) {
        if (tid < s2) {
#pragma unroll
            for (int e = 0; e < 8; e++) red[tid][e] += red[tid + s2][e];
        }
        __syncthreads();
    }
    if (tid < 8) {
        float v = red[0][tid] * (1.f / 128.f) + b3[tid];
        g_logits[c * 8 + tid] = v;
        out[OFF_CLOG + c * 8 + tid] = v;
    }
}

// Parallel stats: 1 CTA, 128 threads (one per chunk). Entropy + argmax per
// chunk in parallel; only the 32-step hysteresis scan is serial (4 threads,
// all data smem-resident).
__global__ void stats_kernel(float* __restrict__ out) {
    const int tid = threadIdx.x;   // 128
    __shared__ float slog[NCHUNK][8];
    __shared__ float sent[NCHUNK];
    __shared__ int stop[NCHUNK];
    __shared__ int sfin[NCHUNK];
    __shared__ int sflip[4];
    __shared__ float sutil[8];

    float lg[8];
#pragma unroll
    for (int e = 0; e < 8; e++) {
        lg[e] = g_logits[tid * 8 + e];
        slog[tid][e] = lg[e];
    }
    // argmax per chunk
    int top = 0;
    float best = lg[0];
#pragma unroll
    for (int e = 1; e < 8; e++)
        if (lg[e] > best) { best = lg[e]; top = e; }
    stop[tid] = top;
    // softmax entropy per chunk
    float ex[8], se = 0.f;
#pragma unroll
    for (int e = 0; e < 8; e++) { ex[e] = expf(lg[e] - best); se += ex[e]; }
    float inv = 1.f / se;
    float ent = 0.f;
#pragma unroll
    for (int e = 0; e < 8; e++) {
        float p = ex[e] * inv;
        ent -= p * logf(p + 1e-8f);
    }
    sent[tid] = ent;
    __syncthreads();

    // sequential hysteresis per batch (4 threads, 32 steps each)
    if (tid < 4) {
        int prev = 0, flips = 0;
        for (int c = 0; c < CSEQ; c++) {
            int idx = tid * CSEQ + c;
            int t = stop[idx];
            int fin;
            if (c == 0) {
                fin = t;
            } else {
                bool sw = (slog[idx][t] - slog[idx][prev]) > 0.7f;
                flips += sw;
                fin = sw ? t : prev;
            }
            prev = fin;
            sfin[idx] = fin;
        }
        sflip[tid] = flips;
    }
    __syncthreads();

    g_expert[tid] = sfin[tid];
    out[OFF_EIDX + tid] = (float)sfin[tid];

    // entropy reduction
    for (int s2 = 64; s2 > 0; s2 >>= 1) {
        if (tid < s2) sent[tid] += sent[tid + s2];
        __syncthreads();
    }
    // utilization per expert
    if (tid < 8) {
        int c = 0;
        for (int i = 0; i < NCHUNK; i++) c += (sfin[i] == tid);
        float u = (float)c / (float)NCHUNK;
        sutil[tid] = u;
        out[OFF_UTIL + tid] = u;
    }
    __syncthreads();
    if (tid == 0) {
        out[OFF_ENT] = sent[0] / (float)NCHUNK;
        float nrm = 0.f;
#pragma unroll
        for (int e = 0; e < 8; e++) nrm += sutil[e] * sutil[e];
        out[OFF_CONC] = sqrtf(nrm);
        out[OFF_FLIP] = (float)(sflip[0] + sflip[1] + sflip[2] + sflip[3]) / (4.f * 31.f);
    }
}

// routing_weights[b][s][e] = one_hot(expert[b][s/128])  -> 131072 floats
__global__ void rw_kernel(float* __restrict__ out) {
    int i = blockIdx.x * blockDim.x + threadIdx.x;  // float4 index, 32768 total
    int o = i << 2;
    int ex = g_expert[o >> 10];   // o / (128 tokens * 8 experts)
    int e0 = o & 7;
    float4 v;
    v.x = (e0 == ex) ? 1.f : 0.f;
    v.y = (e0 + 1 == ex) ? 1.f : 0.f;
    v.z = (e0 + 2 == ex) ? 1.f : 0.f;
    v.w = (e0 + 3 == ex) ? 1.f : 0.f;
    ((float4*)(out + OFF_RW))[i] = v;
}

extern "C" void kernel_launch(void* const* d_in, const int* in_sizes, int n_in,
                              void* d_out, int out_size) {
    const float* x  = (const float*)d_in[0];
    // d_in[1] = prev_expert_indices: given => hysteresis active from chunk 1;
    // its values do not enter the reference computation.
    const float* w1 = (const float*)d_in[2];
    const float* b1 = (const float*)d_in[3];
    const float* w2 = (const float*)d_in[4];
    const float* b2 = (const float*)d_in[5];
    const float* w3 = (const float*)d_in[6];
    const float* b3 = (const float*)d_in[7];
    float* out = (float*)d_out;

    float *h1, *w1r, *w2r, *S;
    cudaGetSymbolAddress((void**)&h1, g_h1);
    cudaGetSymbolAddress((void**)&w1r, g_w1r);
    cudaGetSymbolAddress((void**)&w2r, g_w2r);
    cudaGetSymbolAddress((void**)&S, g_S);

    cudaFuncSetAttribute(gemm_relu<0, 1>, cudaFuncAttributeMaxDynamicSharedMemorySize,
                         SMEM_BYTES);
    cudaFuncSetAttribute(gemm_relu<1, 0>, cudaFuncAttributeMaxDynamicSharedMemorySize,
                         SMEM_BYTES);

    // RNA-round weights into scratch (both GEMM B operands become exact tf32)
    round_weights_kernel<<<(DIM * HID / 4 + HID * HID2 / 4 + 255) / 256, 256>>>(w1, w2);

    // GEMM1: h1 = tf32(relu(x @ w1r + b1))   [16384,2048]x[2048,1024], A cvt in regs
    gemm_relu<0, 1><<<dim3(HID / BN, NTOK / BM), 256, SMEM_BYTES>>>(
        x, w1r, b1, h1, nullptr, NTOK, HID, DIM);
    // GEMM2: S[chunk][n] = sum_{128 tokens} relu(h1 @ w2r + b2)  (no in-loop cvts)
    gemm_relu<1, 0><<<dim3(HID2 / BN, NTOK / BM), 256, SMEM_BYTES>>>(
        h1, w2r, b2, nullptr, S, NTOK, HID2, HID);
    // chunk logits via linearity of the final layer
    chunk_logits_kernel<<<NCHUNK, 256>>>(w3, b3, out);
    // argmax / hysteresis / stats
    stats_kernel<<<1, 128>>>(out);
    // one-hot routing weights
    rw_kernel<<<128, 256>>>(out);
}

// round 8
// speedup vs baseline: 1.2436x; 1.0357x over previous
#include <cuda_runtime.h>
#include <cuda_bf16.h>
#include <math.h>
#include <stdint.h>

// ---------------------------------------------------------------------------
// ChunkStickyRouter (sm_103 legacy tensor path) — R8: tf32 mma.sync m16n8k8
// with ldmatrix.x4 fragment loads (4x fewer shared-pipe issues) and 2 CTAs/SM.
// Proven tf32 numerics (rel_err 8.9e-5). bf16 disqualified (1.34e-3, R7).
// MLP 2048->1024->512->(8 via linearity), chunk-mean folded into GEMM2.
// ---------------------------------------------------------------------------

#define NTOK  16384
#define DIM   2048
#define HID   1024
#define HID2  512
#define NCHUNK 128
#define CSEQ   32

#define BM 128
#define BN 128
#define BK 32
#define LDW 36                          // floats per smem row (144B, LDSM conflict-free)
#define TILE_BYTES (128 * LDW * 4)      // 18432 per operand
#define STAGE_BYTES (2 * TILE_BYTES)    // A + B
#define NSTAGE 3
#define DYN_SMEM (NSTAGE * STAGE_BYTES) // 110592

// output layout
#define OFF_RW    0
#define OFF_EIDX  131072
#define OFF_CLOG  131200
#define OFF_ENT   132224
#define OFF_UTIL  132225
#define OFF_FLIP  132233
#define OFF_CONC  132234

// scratch (no cudaMalloc allowed)
__device__ float g_h1[(size_t)NTOK * HID];    // 64 MB, stored tf32-rounded
__device__ float g_w1t[(size_t)HID * DIM];    // w1^T [N,K], RNA-rounded
__device__ float g_w2t[(size_t)HID2 * HID];   // w2^T [N,K], RNA-rounded
__device__ float g_S[NCHUNK * HID2];
__device__ float g_logits[NCHUNK * 8];
__device__ int   g_expert[NCHUNK];

__device__ __forceinline__ float to_tf32(float x) {
    asm("cvt.rna.tf32.f32 %0, %0;" : "+f"(x));
    return x;
}
__device__ __forceinline__ unsigned to_tf32_u(unsigned x) {
    float f = __uint_as_float(x);
    asm("cvt.rna.tf32.f32 %0, %0;" : "+f"(f));
    return __float_as_uint(f);
}
__device__ __forceinline__ uint32_t smem_u32(const void* p) {
    return (uint32_t)__cvta_generic_to_shared(p);
}
__device__ __forceinline__ void cp16(uint32_t dst, const void* src) {
    asm volatile("cp.async.cg.shared.global [%0], [%1], 16;\n" :: "r"(dst), "l"(src));
}
__device__ __forceinline__ void ldsm4(unsigned& r0, unsigned& r1, unsigned& r2, unsigned& r3,
                                      uint32_t addr) {
    asm volatile("ldmatrix.sync.aligned.m8n8.x4.shared.b16 {%0,%1,%2,%3}, [%4];"
                 : "=r"(r0), "=r"(r1), "=r"(r2), "=r"(r3) : "r"(addr));
}
__device__ __forceinline__ void mma_tf32(float& d0, float& d1, float& d2, float& d3,
                                         unsigned a0, unsigned a1, unsigned a2, unsigned a3,
                                         unsigned b0, unsigned b1) {
    asm volatile(
        "mma.sync.aligned.m16n8k8.row.col.f32.tf32.tf32.f32 "
        "{%0,%1,%2,%3},{%4,%5,%6,%7},{%8,%9},{%0,%1,%2,%3};\n"
        : "+f"(d0), "+f"(d1), "+f"(d2), "+f"(d3)
        : "r"(a0), "r"(a1), "r"(a2), "r"(a3), "r"(b0), "r"(b1));
}

// WT[n][k] = tf32(W[k][n]); W is [R x Ccols] fp32
__global__ void transpose_round(const float* __restrict__ W, float* __restrict__ WT,
                                int R, int Ccols) {
    __shared__ float t[32][33];
    const int tx = threadIdx.x, ty = threadIdx.y;       // (32, 8)
    const int rc = blockIdx.x * 32, cc = blockIdx.y * 32;
#pragma unroll
    for (int i = 0; i < 4; i++)
        t[ty + 8 * i][tx] = W[(size_t)(rc + ty + 8 * i) * Ccols + cc + tx];
    __syncthreads();
#pragma unroll
    for (int i = 0; i < 4; i++)
        WT[(size_t)(cc + ty + 8 * i) * R + rc + tx] = to_tf32(t[tx][ty + 8 * i]);
}

// tf32 GEMM: C = A[M,K] @ Bt[N,K]^T, 3-stage cp.async, ldmatrix frags, occ 2.
// EPI 0: C = tf32(relu(acc + bias)) full store (h1); EPI 1: per-chunk col sums.
// CVT_A 1: RNA-round A frags in regs (x raw); 0: A pre-rounded (h1).
template <int EPI, int CVT_A>
__global__ __launch_bounds__(256, 2)
void gemm_tf32(const float* __restrict__ A, const float* __restrict__ Bt,
               const float* __restrict__ bias, float* __restrict__ C,
               float* __restrict__ Sout, int M, int N_total, int K) {
    extern __shared__ __align__(16) char smem[];
    __shared__ float s_colsum[BN];

    const int tid = threadIdx.x;
    const int warp = tid >> 5;
    const int lane = tid & 31;
    const int quad = lane >> 3;      // 0..3 (ldmatrix matrix select)
    const int rsel = lane & 7;       // row within matrix
    const int warpM = warp >> 2;     // 0..1 (64 rows)
    const int warpN = warp & 3;      // 0..3 (32 cols)
    const int bn = blockIdx.x, bm = blockIdx.y;

    if (EPI == 1 && tid < BN) s_colsum[tid] = 0.f;

    float acc[4][4][4];
#pragma unroll
    for (int i = 0; i < 4; i++)
#pragma unroll
        for (int j = 0; j < 4; j++)
#pragma unroll
            for (int r = 0; r < 4; r++) acc[i][j][r] = 0.f;

    const float* Ablk = A + (size_t)bm * BM * K;
    const float* Bblk = Bt + (size_t)bn * BN * K;

    const uint32_t smem_base = smem_u32(smem);
    // cp.async coords: 1024 16B-chunks per operand, 4 per thread
    const int crow = tid >> 3;          // +32 per i
    const int cc8 = (tid & 7) * 16;     // byte offset within 128B of row data
    const int cc4f = (tid & 7) * 4;     // float offset in gmem row

    auto issue = [&](int t) {
        const uint32_t st = smem_base + (t % NSTAGE) * STAGE_BYTES;
        const float* Ag = Ablk + (size_t)t * BK;
        const float* Bg = Bblk + (size_t)t * BK;
#pragma unroll
        for (int i = 0; i < 4; i++) {
            int r = crow + 32 * i;
            cp16(st + r * (LDW * 4) + cc8, Ag + (size_t)r * K + cc4f);
        }
#pragma unroll
        for (int i = 0; i < 4; i++) {
            int r = crow + 32 * i;
            cp16(st + TILE_BYTES + r * (LDW * 4) + cc8, Bg + (size_t)r * K + cc4f);
        }
        asm volatile("cp.async.commit_group;\n");
    };

    // ldmatrix per-thread address offsets (floats)
    const int a_roff = (quad & 1) * 8 + rsel;   // row offset within 16-row mi block
    const int a_coff = (quad >> 1) * 4;         // col offset (k)
    const int b_roff = (quad >> 1) * 8 + rsel;  // row offset within 16-row ni-pair
    const int b_coff = (quad & 1) * 4;

    auto compute_tile = [&](int t) {
        const uint32_t aS = smem_base + (t % NSTAGE) * STAGE_BYTES;
        const uint32_t bS = aS + TILE_BYTES;
#pragma unroll
        for (int kk = 0; kk < 4; kk++) {
            const int k0 = kk * 8;
            unsigned af[4][4], bf[4][2];
#pragma unroll
            for (int mi = 0; mi < 4; mi++) {
                uint32_t addr = aS + ((warpM * 64 + mi * 16 + a_roff) * LDW + k0 + a_coff) * 4;
                ldsm4(af[mi][0], af[mi][1], af[mi][2], af[mi][3], addr);
                if (CVT_A) {
                    af[mi][0] = to_tf32_u(af[mi][0]);
                    af[mi][1] = to_tf32_u(af[mi][1]);
                    af[mi][2] = to_tf32_u(af[mi][2]);
                    af[mi][3] = to_tf32_u(af[mi][3]);
                }
            }
#pragma unroll
            for (int nip = 0; nip < 4; nip += 2) {
                uint32_t addr = bS + ((warpN * 32 + nip * 8 + b_roff) * LDW + k0 + b_coff) * 4;
                ldsm4(bf[nip][0], bf[nip][1], bf[nip + 1][0], bf[nip + 1][1], addr);
            }
#pragma unroll
            for (int mi = 0; mi < 4; mi++)
#pragma unroll
                for (int ni = 0; ni < 4; ni++)
                    mma_tf32(acc[mi][ni][0], acc[mi][ni][1], acc[mi][ni][2], acc[mi][ni][3],
                             af[mi][0], af[mi][1], af[mi][2], af[mi][3],
                             bf[ni][0], bf[ni][1]);
        }
    };

    const int KT = K / BK;
    issue(0);
    issue(1);
    for (int t = 0; t < KT; t++) {
        asm volatile("cp.async.wait_group 1;\n");
        __syncthreads();
        if (t + 2 < KT) issue(t + 2);
        else asm volatile("cp.async.commit_group;\n");
        compute_tile(t);
    }

    const int g = lane >> 2, tg = lane & 3;
    if (EPI == 0) {
#pragma unroll
        for (int mi = 0; mi < 4; mi++) {
            int mrow = bm * BM + warpM * 64 + mi * 16 + g;
#pragma unroll
            for (int ni = 0; ni < 4; ni++) {
                int ncol = bn * BN + warpN * 32 + ni * 8 + 2 * tg;
                float bv0 = bias[ncol], bv1 = bias[ncol + 1];
                float2 v0 = {to_tf32(fmaxf(acc[mi][ni][0] + bv0, 0.f)),
                             to_tf32(fmaxf(acc[mi][ni][1] + bv1, 0.f))};
                float2 v1 = {to_tf32(fmaxf(acc[mi][ni][2] + bv0, 0.f)),
                             to_tf32(fmaxf(acc[mi][ni][3] + bv1, 0.f))};
                *(float2*)(C + (size_t)mrow * N_total + ncol) = v0;
                *(float2*)(C + (size_t)(mrow + 8) * N_total + ncol) = v1;
            }
        }
    } else {
#pragma unroll
        for (int ni = 0; ni < 4; ni++) {
#pragma unroll
            for (int p = 0; p < 2; p++) {
                int nloc = warpN * 32 + ni * 8 + 2 * tg + p;
                float bv = bias[bn * BN + nloc];
                float s = 0.f;
#pragma unroll
                for (int mi = 0; mi < 4; mi++) {
                    s += fmaxf(acc[mi][ni][p] + bv, 0.f);
                    s += fmaxf(acc[mi][ni][p + 2] + bv, 0.f);
                }
                s += __shfl_xor_sync(0xffffffffu, s, 4);
                s += __shfl_xor_sync(0xffffffffu, s, 8);
                s += __shfl_xor_sync(0xffffffffu, s, 16);
                if (g == 0) atomicAdd(&s_colsum[nloc], s);
            }
        }
        __syncthreads();
        if (tid < BN)
            Sout[(size_t)bm * N_total + bn * BN + tid] = s_colsum[tid];
    }
}

// chunk_logits[c][e] = (1/128) * S[c][:] . w3[:,e] + b3[e]
__global__ void chunk_logits_kernel(const float* __restrict__ w3,
                                    const float* __restrict__ b3,
                                    float* __restrict__ out) {
    const int c = blockIdx.x;
    const int tid = threadIdx.x; // 256
    float partial[8];
#pragma unroll
    for (int e = 0; e < 8; e++) partial[e] = 0.f;
    for (int k = tid; k < HID2; k += 256) {
        float sv = g_S[c * HID2 + k];
        float4 wa = *(const float4*)(w3 + k * 8);
        float4 wb = *(const float4*)(w3 + k * 8 + 4);
        partial[0] += sv * wa.x; partial[1] += sv * wa.y;
        partial[2] += sv * wa.z; partial[3] += sv * wa.w;
        partial[4] += sv * wb.x; partial[5] += sv * wb.y;
        partial[6] += sv * wb.z; partial[7] += sv * wb.w;
    }
    __shared__ float red[256][8];
#pragma unroll
    for (int e = 0; e < 8; e++) red[tid][e] = partial[e];
    __syncthreads();
    for (int s2 = 128; s2 > 0; s2 >>= 1) {
        if (tid < s2) {
#pragma unroll
            for (int e = 0; e < 8; e++) red[tid][e] += red[tid + s2][e];
        }
        __syncthreads();
    }
    if (tid < 8) {
        float v = red[0][tid] * (1.f / 128.f) + b3[tid];
        g_logits[c * 8 + tid] = v;
        out[OFF_CLOG + c * 8 + tid] = v;
    }
}

// stats: entropy/argmax parallel; 32-step hysteresis serial (4 threads)
__global__ void stats_kernel(float* __restrict__ out) {
    const int tid = threadIdx.x;   // 128
    __shared__ float slog[NCHUNK][8];
    __shared__ float sent[NCHUNK];
    __shared__ int stop[NCHUNK];
    __shared__ int sfin[NCHUNK];
    __shared__ int sflip[4];
    __shared__ float sutil[8];

    float lg[8];
#pragma unroll
    for (int e = 0; e < 8; e++) {
        lg[e] = g_logits[tid * 8 + e];
        slog[tid][e] = lg[e];
    }
    int top = 0;
    float best = lg[0];
#pragma unroll
    for (int e = 1; e < 8; e++)
        if (lg[e] > best) { best = lg[e]; top = e; }
    stop[tid] = top;
    float ex[8], se = 0.f;
#pragma unroll
    for (int e = 0; e < 8; e++) { ex[e] = expf(lg[e] - best); se += ex[e]; }
    float inv = 1.f / se;
    float ent = 0.f;
#pragma unroll
    for (int e = 0; e < 8; e++) {
        float p = ex[e] * inv;
        ent -= p * logf(p + 1e-8f);
    }
    sent[tid] = ent;
    __syncthreads();

    if (tid < 4) {
        int prev = 0, flips = 0;
        for (int c = 0; c < CSEQ; c++) {
            int idx = tid * CSEQ + c;
            int t = stop[idx];
            int fin;
            if (c == 0) fin = t;
            else {
                bool sw = (slog[idx][t] - slog[idx][prev]) > 0.7f;
                flips += sw;
                fin = sw ? t : prev;
            }
            prev = fin;
            sfin[idx] = fin;
        }
        sflip[tid] = flips;
    }
    __syncthreads();

    g_expert[tid] = sfin[tid];
    out[OFF_EIDX + tid] = (float)sfin[tid];

    for (int s2 = 64; s2 > 0; s2 >>= 1) {
        if (tid < s2) sent[tid] += sent[tid + s2];
        __syncthreads();
    }
    if (tid < 8) {
        int c = 0;
        for (int i = 0; i < NCHUNK; i++) c += (sfin[i] == tid);
        float u = (float)c / (float)NCHUNK;
        sutil[tid] = u;
        out[OFF_UTIL + tid] = u;
    }
    __syncthreads();
    if (tid == 0) {
        out[OFF_ENT] = sent[0] / (float)NCHUNK;
        float nrm = 0.f;
#pragma unroll
        for (int e = 0; e < 8; e++) nrm += sutil[e] * sutil[e];
        out[OFF_CONC] = sqrtf(nrm);
        out[OFF_FLIP] = (float)(sflip[0] + sflip[1] + sflip[2] + sflip[3]) / (4.f * 31.f);
    }
}

__global__ void rw_kernel(float* __restrict__ out) {
    int i = blockIdx.x * blockDim.x + threadIdx.x;
    int o = i << 2;
    int ex = g_expert[o >> 10];
    int e0 = o & 7;
    float4 v;
    v.x = (e0 == ex) ? 1.f : 0.f;
    v.y = (e0 + 1 == ex) ? 1.f : 0.f;
    v.z = (e0 + 2 == ex) ? 1.f : 0.f;
    v.w = (e0 + 3 == ex) ? 1.f : 0.f;
    ((float4*)(out + OFF_RW))[i] = v;
}

extern "C" void kernel_launch(void* const* d_in, const int* in_sizes, int n_in,
                              void* d_out, int out_size) {
    const float* x  = (const float*)d_in[0];
    // d_in[1] = prev_expert_indices: presence => hysteresis; values unused.
    const float* w1 = (const float*)d_in[2];
    const float* b1 = (const float*)d_in[3];
    const float* w2 = (const float*)d_in[4];
    const float* b2 = (const float*)d_in[5];
    const float* w3 = (const float*)d_in[6];
    const float* b3 = (const float*)d_in[7];
    float* out = (float*)d_out;

    float *h1, *w1t, *w2t, *S;
    cudaGetSymbolAddress((void**)&h1, g_h1);
    cudaGetSymbolAddress((void**)&w1t, g_w1t);
    cudaGetSymbolAddress((void**)&w2t, g_w2t);
    cudaGetSymbolAddress((void**)&S, g_S);

    cudaFuncSetAttribute(gemm_tf32<0, 1>, cudaFuncAttributeMaxDynamicSharedMemorySize, DYN_SMEM);
    cudaFuncSetAttribute(gemm_tf32<1, 0>, cudaFuncAttributeMaxDynamicSharedMemorySize, DYN_SMEM);

    // one-time: transpose + RNA-round weights to K-major [N,K]
    transpose_round<<<dim3(DIM / 32, HID / 32), dim3(32, 8)>>>(w1, w1t, DIM, HID);
    transpose_round<<<dim3(HID / 32, HID2 / 32), dim3(32, 8)>>>(w2, w2t, HID, HID2);

    // GEMM1: h1 = tf32(relu(x @ w1 + b1)); x rounded in regs post-ldmatrix
    gemm_tf32<0, 1><<<dim3(HID / BN, NTOK / BM), 256, DYN_SMEM>>>(
        x, w1t, b1, h1, nullptr, NTOK, HID, DIM);
    // GEMM2: S[chunk] = col-sums of relu(h1 @ w2 + b2); h2 never stored
    gemm_tf32<1, 0><<<dim3(HID2 / BN, NTOK / BM), 256, DYN_SMEM>>>(
        h1, w2t, b2, nullptr, S, NTOK, HID2, HID);

    chunk_logits_kernel<<<NCHUNK, 256>>>(w3, b3, out);
    stats_kernel<<<1, 128>>>(out);
    rw_kernel<<<128, 256>>>(out);
}

// round 9
// speedup vs baseline: 2.2859x; 1.8381x over previous
#include <cuda_runtime.h>
#include <cuda_fp16.h>
#include <math.h>
#include <stdint.h>

// ---------------------------------------------------------------------------
// ChunkStickyRouter (sm_103 legacy tensor path) — R9: fp16 mma.sync m16n8k16.
// fp16 mantissa (10 bits) == tf32 mantissa => same numerics class as the
// measured 8.9e-5 tf32 run, at 2x MACs/instr and half the bytes.
// (bf16 = 7 bits was disqualified at 1.34e-3 in R7.)
// Skeleton from R8: 3-stage cp.async, ldmatrix.x4, 2 CTAs/SM.
// ---------------------------------------------------------------------------

#define NTOK  16384
#define DIM   2048
#define HID   1024
#define HID2  512
#define NCHUNK 128
#define CSEQ   32

#define BM 128
#define BN 128
#define BK 64                           // halfs (128B gmem row per tile)
#define LDW 72                          // halfs per smem row (144B, LDSM conflict-free)
#define TILE_BYTES (128 * LDW * 2)      // 18432 per operand
#define STAGE_BYTES (2 * TILE_BYTES)
#define NSTAGE 3
#define DYN_SMEM (NSTAGE * STAGE_BYTES) // 110592

// output layout
#define OFF_RW    0
#define OFF_EIDX  131072
#define OFF_CLOG  131200
#define OFF_ENT   132224
#define OFF_UTIL  132225
#define OFF_FLIP  132233
#define OFF_CONC  132234

// scratch (no cudaMalloc allowed)
__device__ __half g_xh[(size_t)NTOK * DIM];    // x in fp16 (64 MB)
__device__ __half g_h1[(size_t)NTOK * HID];    // hidden1 fp16 (32 MB)
__device__ __half g_w1t[(size_t)HID * DIM];    // w1^T [N,K] fp16
__device__ __half g_w2t[(size_t)HID2 * HID];   // w2^T [N,K] fp16
__device__ float g_S[NCHUNK * HID2];
__device__ float g_logits[NCHUNK * 8];
__device__ int   g_expert[NCHUNK];

__device__ __forceinline__ uint32_t smem_u32(const void* p) {
    return (uint32_t)__cvta_generic_to_shared(p);
}
__device__ __forceinline__ void cp16(uint32_t dst, const void* src) {
    asm volatile("cp.async.cg.shared.global [%0], [%1], 16;\n" :: "r"(dst), "l"(src));
}
__device__ __forceinline__ void ldsm4(unsigned& r0, unsigned& r1, unsigned& r2, unsigned& r3,
                                      uint32_t addr) {
    asm volatile("ldmatrix.sync.aligned.m8n8.x4.shared.b16 {%0,%1,%2,%3}, [%4];"
                 : "=r"(r0), "=r"(r1), "=r"(r2), "=r"(r3) : "r"(addr));
}
__device__ __forceinline__ void mma_f16(float& d0, float& d1, float& d2, float& d3,
                                        unsigned a0, unsigned a1, unsigned a2, unsigned a3,
                                        unsigned b0, unsigned b1) {
    asm volatile(
        "mma.sync.aligned.m16n8k16.row.col.f32.f16.f16.f32 "
        "{%0,%1,%2,%3},{%4,%5,%6,%7},{%8,%9},{%0,%1,%2,%3};\n"
        : "+f"(d0), "+f"(d1), "+f"(d2), "+f"(d3)
        : "r"(a0), "r"(a1), "r"(a2), "r"(a3), "r"(b0), "r"(b1));
}
__device__ __forceinline__ uint32_t pack_f16(float lo, float hi) {
    __half2 h = __floats2half2_rn(lo, hi);
    return *(uint32_t*)&h;
}

// x fp32 -> fp16 (RN), 8 elems/thread
__global__ void convert_x(const float* __restrict__ x) {
    size_t i = (size_t)blockIdx.x * blockDim.x + threadIdx.x;
    float4 v0 = ((const float4*)x)[2 * i];
    float4 v1 = ((const float4*)x)[2 * i + 1];
    uint4 o;
    o.x = pack_f16(v0.x, v0.y);
    o.y = pack_f16(v0.z, v0.w);
    o.z = pack_f16(v1.x, v1.y);
    o.w = pack_f16(v1.z, v1.w);
    ((uint4*)g_xh)[i] = o;
}

// WT[n][k] = fp16(W[k][n]); W is [R x Ccols] fp32
__global__ void transpose_cvt(const float* __restrict__ W, __half* __restrict__ WT,
                              int R, int Ccols) {
    __shared__ float t[32][33];
    const int tx = threadIdx.x, ty = threadIdx.y;       // (32, 8)
    const int rc = blockIdx.x * 32, cc = blockIdx.y * 32;
#pragma unroll
    for (int i = 0; i < 4; i++)
        t[ty + 8 * i][tx] = W[(size_t)(rc + ty + 8 * i) * Ccols + cc + tx];
    __syncthreads();
#pragma unroll
    for (int i = 0; i < 4; i++)
        WT[(size_t)(cc + ty + 8 * i) * R + rc + tx] = __float2half_rn(t[tx][ty + 8 * i]);
}

// fp16 GEMM: C = A[M,K] @ Bt[N,K]^T. 3-stage cp.async, ldmatrix frags, occ 2.
// EPI 0: C = fp16(relu(acc + bias)) full store (h1); EPI 1: per-chunk col sums.
template <int EPI>
__global__ __launch_bounds__(256, 2)
void gemm_f16(const __half* __restrict__ A, const __half* __restrict__ Bt,
              const float* __restrict__ bias, __half* __restrict__ C,
              float* __restrict__ Sout, int M, int N_total, int K) {
    extern __shared__ __align__(16) char smem[];
    __shared__ float s_colsum[BN];

    const int tid = threadIdx.x;
    const int warp = tid >> 5;
    const int lane = tid & 31;
    const int quad = lane >> 3;
    const int rsel = lane & 7;
    const int warpM = warp >> 2;     // 0..1 (64 rows)
    const int warpN = warp & 3;      // 0..3 (32 cols)
    const int bn = blockIdx.x, bm = blockIdx.y;

    if (EPI == 1 && tid < BN) s_colsum[tid] = 0.f;

    float acc[4][4][4];
#pragma unroll
    for (int i = 0; i < 4; i++)
#pragma unroll
        for (int j = 0; j < 4; j++)
#pragma unroll
            for (int r = 0; r < 4; r++) acc[i][j][r] = 0.f;

    const __half* Ablk = A + (size_t)bm * BM * K;
    const __half* Bblk = Bt + (size_t)bn * BN * K;

    const uint32_t smem_base = smem_u32(smem);
    // cp.async coords: each row 128B = 8 chunks; 1024 chunks/operand, 4/thread
    const int crow = tid >> 3;          // +32 per i
    const int ccb = (tid & 7) * 16;     // byte offset in smem row
    const int cch = (tid & 7) * 8;      // half offset in gmem row

    auto issue = [&](int t) {
        const uint32_t st = smem_base + (t % NSTAGE) * STAGE_BYTES;
        const __half* Ag = Ablk + (size_t)t * BK;
        const __half* Bg = Bblk + (size_t)t * BK;
#pragma unroll
        for (int i = 0; i < 4; i++) {
            int r = crow + 32 * i;
            cp16(st + r * (LDW * 2) + ccb, Ag + (size_t)r * K + cch);
        }
#pragma unroll
        for (int i = 0; i < 4; i++) {
            int r = crow + 32 * i;
            cp16(st + TILE_BYTES + r * (LDW * 2) + ccb, Bg + (size_t)r * K + cch);
        }
        asm volatile("cp.async.commit_group;\n");
    };

    // ldmatrix per-thread offsets (halfs)
    const int a_roff = (quad & 1) * 8 + rsel;   // A: q0=(m,k) q1=(m+8,k) q2=(m,k+8) q3=(m+8,k+8)
    const int a_coff = (quad >> 1) * 8;
    const int b_roff = (quad >> 1) * 8 + rsel;  // B: q0=(n,k) q1=(n,k+8) q2=(n+8,k) q3=(n+8,k+8)
    const int b_coff = (quad & 1) * 8;

    auto compute_tile = [&](int t) {
        const uint32_t aS = smem_base + (t % NSTAGE) * STAGE_BYTES;
        const uint32_t bS = aS + TILE_BYTES;
#pragma unroll
        for (int ks = 0; ks < 4; ks++) {
            const int k0 = ks * 16;
            unsigned af[4][4], bf[4][2];
#pragma unroll
            for (int mi = 0; mi < 4; mi++) {
                uint32_t addr = aS + ((warpM * 64 + mi * 16 + a_roff) * LDW + k0 + a_coff) * 2;
                ldsm4(af[mi][0], af[mi][1], af[mi][2], af[mi][3], addr);
            }
#pragma unroll
            for (int nip = 0; nip < 4; nip += 2) {
                uint32_t addr = bS + ((warpN * 32 + nip * 8 + b_roff) * LDW + k0 + b_coff) * 2;
                ldsm4(bf[nip][0], bf[nip][1], bf[nip + 1][0], bf[nip + 1][1], addr);
            }
#pragma unroll
            for (int mi = 0; mi < 4; mi++)
#pragma unroll
                for (int ni = 0; ni < 4; ni++)
                    mma_f16(acc[mi][ni][0], acc[mi][ni][1], acc[mi][ni][2], acc[mi][ni][3],
                            af[mi][0], af[mi][1], af[mi][2], af[mi][3],
                            bf[ni][0], bf[ni][1]);
        }
    };

    const int KT = K / BK;
    issue(0);
    issue(1);
    for (int t = 0; t < KT; t++) {
        asm volatile("cp.async.wait_group 1;\n");
        __syncthreads();
        if (t + 2 < KT) issue(t + 2);
        else asm volatile("cp.async.commit_group;\n");
        compute_tile(t);
    }

    const int g = lane >> 2, tg = lane & 3;
    if (EPI == 0) {
#pragma unroll
        for (int mi = 0; mi < 4; mi++) {
            int mrow = bm * BM + warpM * 64 + mi * 16 + g;
#pragma unroll
            for (int ni = 0; ni < 4; ni++) {
                int ncol = bn * BN + warpN * 32 + ni * 8 + 2 * tg;
                float bv0 = bias[ncol], bv1 = bias[ncol + 1];
                uint32_t p0 = pack_f16(fmaxf(acc[mi][ni][0] + bv0, 0.f),
                                       fmaxf(acc[mi][ni][1] + bv1, 0.f));
                uint32_t p1 = pack_f16(fmaxf(acc[mi][ni][2] + bv0, 0.f),
                                       fmaxf(acc[mi][ni][3] + bv1, 0.f));
                *(uint32_t*)(C + (size_t)mrow * N_total + ncol) = p0;
                *(uint32_t*)(C + (size_t)(mrow + 8) * N_total + ncol) = p1;
            }
        }
    } else {
#pragma unroll
        for (int ni = 0; ni < 4; ni++) {
#pragma unroll
            for (int p = 0; p < 2; p++) {
                int nloc = warpN * 32 + ni * 8 + 2 * tg + p;
                float bv = bias[bn * BN + nloc];
                float s = 0.f;
#pragma unroll
                for (int mi = 0; mi < 4; mi++) {
                    s += fmaxf(acc[mi][ni][p] + bv, 0.f);
                    s += fmaxf(acc[mi][ni][p + 2] + bv, 0.f);
                }
                s += __shfl_xor_sync(0xffffffffu, s, 4);
                s += __shfl_xor_sync(0xffffffffu, s, 8);
                s += __shfl_xor_sync(0xffffffffu, s, 16);
                if (g == 0) atomicAdd(&s_colsum[nloc], s);
            }
        }
        __syncthreads();
        if (tid < BN)
            Sout[(size_t)bm * N_total + bn * BN + tid] = s_colsum[tid];
    }
}

// chunk_logits[c][e] = (1/128) * S[c][:] . w3[:,e] + b3[e]   (fp32 tail)
__global__ void chunk_logits_kernel(const float* __restrict__ w3,
                                    const float* __restrict__ b3,
                                    float* __restrict__ out) {
    const int c = blockIdx.x;
    const int tid = threadIdx.x; // 256
    float partial[8];
#pragma unroll
    for (int e = 0; e < 8; e++) partial[e] = 0.f;
    for (int k = tid; k < HID2; k += 256) {
        float sv = g_S[c * HID2 + k];
        float4 wa = *(const float4*)(w3 + k * 8);
        float4 wb = *(const float4*)(w3 + k * 8 + 4);
        partial[0] += sv * wa.x; partial[1] += sv * wa.y;
        partial[2] += sv * wa.z; partial[3] += sv * wa.w;
        partial[4] += sv * wb.x; partial[5] += sv * wb.y;
        partial[6] += sv * wb.z; partial[7] += sv * wb.w;
    }
    __shared__ float red[256][8];
#pragma unroll
    for (int e = 0; e < 8; e++) red[tid][e] = partial[e];
    __syncthreads();
    for (int s2 = 128; s2 > 0; s2 >>= 1) {
        if (tid < s2) {
#pragma unroll
            for (int e = 0; e < 8; e++) red[tid][e] += red[tid + s2][e];
        }
        __syncthreads();
    }
    if (tid < 8) {
        float v = red[0][tid] * (1.f / 128.f) + b3[tid];
        g_logits[c * 8 + tid] = v;
        out[OFF_CLOG + c * 8 + tid] = v;
    }
}

// stats: entropy/argmax parallel; 32-step hysteresis serial (4 threads)
__global__ void stats_kernel(float* __restrict__ out) {
    const int tid = threadIdx.x;   // 128
    __shared__ float slog[NCHUNK][8];
    __shared__ float sent[NCHUNK];
    __shared__ int stop[NCHUNK];
    __shared__ int sfin[NCHUNK];
    __shared__ int sflip[4];
    __shared__ float sutil[8];

    float lg[8];
#pragma unroll
    for (int e = 0; e < 8; e++) {
        lg[e] = g_logits[tid * 8 + e];
        slog[tid][e] = lg[e];
    }
    int top = 0;
    float best = lg[0];
#pragma unroll
    for (int e = 1; e < 8; e++)
        if (lg[e] > best) { best = lg[e]; top = e; }
    stop[tid] = top;
    float ex[8], se = 0.f;
#pragma unroll
    for (int e = 0; e < 8; e++) { ex[e] = expf(lg[e] - best); se += ex[e]; }
    float inv = 1.f / se;
    float ent = 0.f;
#pragma unroll
    for (int e = 0; e < 8; e++) {
        float p = ex[e] * inv;
        ent -= p * logf(p + 1e-8f);
    }
    sent[tid] = ent;
    __syncthreads();

    if (tid < 4) {
        int prev = 0, flips = 0;
        for (int c = 0; c < CSEQ; c++) {
            int idx = tid * CSEQ + c;
            int t = stop[idx];
            int fin;
            if (c == 0) fin = t;
            else {
                bool sw = (slog[idx][t] - slog[idx][prev]) > 0.7f;
                flips += sw;
                fin = sw ? t : prev;
            }
            prev = fin;
            sfin[idx] = fin;
        }
        sflip[tid] = flips;
    }
    __syncthreads();

    g_expert[tid] = sfin[tid];
    out[OFF_EIDX + tid] = (float)sfin[tid];

    for (int s2 = 64; s2 > 0; s2 >>= 1) {
        if (tid < s2) sent[tid] += sent[tid + s2];
        __syncthreads();
    }
    if (tid < 8) {
        int c = 0;
        for (int i = 0; i < NCHUNK; i++) c += (sfin[i] == tid);
        float u = (float)c / (float)NCHUNK;
        sutil[tid] = u;
        out[OFF_UTIL + tid] = u;
    }
    __syncthreads();
    if (tid == 0) {
        out[OFF_ENT] = sent[0] / (float)NCHUNK;
        float nrm = 0.f;
#pragma unroll
        for (int e = 0; e < 8; e++) nrm += sutil[e] * sutil[e];
        out[OFF_CONC] = sqrtf(nrm);
        out[OFF_FLIP] = (float)(sflip[0] + sflip[1] + sflip[2] + sflip[3]) / (4.f * 31.f);
    }
}

__global__ void rw_kernel(float* __restrict__ out) {
    int i = blockIdx.x * blockDim.x + threadIdx.x;
    int o = i << 2;
    int ex = g_expert[o >> 10];
    int e0 = o & 7;
    float4 v;
    v.x = (e0 == ex) ? 1.f : 0.f;
    v.y = (e0 + 1 == ex) ? 1.f : 0.f;
    v.z = (e0 + 2 == ex) ? 1.f : 0.f;
    v.w = (e0 + 3 == ex) ? 1.f : 0.f;
    ((float4*)(out + OFF_RW))[i] = v;
}

extern "C" void kernel_launch(void* const* d_in, const int* in_sizes, int n_in,
                              void* d_out, int out_size) {
    const float* x  = (const float*)d_in[0];
    // d_in[1] = prev_expert_indices: presence => hysteresis; values unused.
    const float* w1 = (const float*)d_in[2];
    const float* b1 = (const float*)d_in[3];
    const float* w2 = (const float*)d_in[4];
    const float* b2 = (const float*)d_in[5];
    const float* w3 = (const float*)d_in[6];
    const float* b3 = (const float*)d_in[7];
    float* out = (float*)d_out;

    __half *xh, *h1, *w1t, *w2t;
    float *S;
    cudaGetSymbolAddress((void**)&xh, g_xh);
    cudaGetSymbolAddress((void**)&h1, g_h1);
    cudaGetSymbolAddress((void**)&w1t, g_w1t);
    cudaGetSymbolAddress((void**)&w2t, g_w2t);
    cudaGetSymbolAddress((void**)&S, g_S);

    cudaFuncSetAttribute(gemm_f16<0>, cudaFuncAttributeMaxDynamicSharedMemorySize, DYN_SMEM);
    cudaFuncSetAttribute(gemm_f16<1>, cudaFuncAttributeMaxDynamicSharedMemorySize, DYN_SMEM);

    // pre-passes: x -> fp16; weights -> transposed fp16 [N,K]
    convert_x<<<(NTOK * (size_t)DIM / 8) / 256, 256>>>(x);
    transpose_cvt<<<dim3(DIM / 32, HID / 32), dim3(32, 8)>>>(w1, w1t, DIM, HID);
    transpose_cvt<<<dim3(HID / 32, HID2 / 32), dim3(32, 8)>>>(w2, w2t, HID, HID2);

    // GEMM1: h1 = fp16(relu(xh @ w1 + b1))
    gemm_f16<0><<<dim3(HID / BN, NTOK / BM), 256, DYN_SMEM>>>(
        xh, w1t, b1, h1, nullptr, NTOK, HID, DIM);
    // GEMM2: S[chunk] = col-sums of relu(h1 @ w2 + b2); h2 never stored
    gemm_f16<1><<<dim3(HID2 / BN, NTOK / BM), 256, DYN_SMEM>>>(
        h1, w2t, b2, nullptr, S, NTOK, HID2, HID);

    chunk_logits_kernel<<<NCHUNK, 256>>>(w3, b3, out);
    stats_kernel<<<1, 128>>>(out);
    rw_kernel<<<128, 256>>>(out);
}